// round 8
// baseline (speedup 1.0000x reference)
#include <cuda_runtime.h>
#include <cuda_bf16.h>

#define TT 2048
#define BB 64
#define GG 192
#define OUT_MAIN 33554432
#define NTILE 8192

typedef unsigned long long ull;

// ---------------- device scratch (no cudaMalloc allowed) ----------------
__device__ float g_gi[(size_t)TT * BB * 768];          // input-side preactivations
__device__ ulonglong2 g_wihA[64 * 96];                 // {(r pair),(i pair)} per (u, col-pair)
__device__ ulonglong2 g_wihB[64 * 96];                 // {(j pair),(k pair)}
__device__ ulonglong2 g_whhA[64 * 96];
__device__ ulonglong2 g_whhB[64 * 96];

// ---------------- helpers ----------------
__device__ __forceinline__ ull pk2(float a, float b) {
    ull r; asm("mov.b64 %0, {%1,%2};" : "=l"(r) : "f"(a), "f"(b)); return r;
}
__device__ __forceinline__ float2 upk2(ull v) {
    float2 r; asm("mov.b64 {%0,%1}, %2;" : "=f"(r.x), "=f"(r.y) : "l"(v)); return r;
}
__device__ __forceinline__ unsigned s2u(const void* p) {
    unsigned a;
    asm("{ .reg .u64 t; cvta.to.shared.u64 t, %1; cvt.u32.u64 %0, t; }" : "=r"(a) : "l"(p));
    return a;
}
#define FMA2(acc, a, b) asm("fma.rn.f32x2 %0, %1, %2, %0;" : "+l"(acc) : "l"(a), "l"(b))

// Full quaternion (Hamilton) product contribution for one u and one column
// pair: 16 packed FMAs. P/N accumulator split avoids operand negation.
#define QFMA16(hr2,hi2,hj2,hk2, wr2,wi2,wj2,wk2, Pr,Nr,Pi,Ni,Pj,Nj,Pk,Nk) do { \
    FMA2(Pr,hr2,wr2); FMA2(Nr,hi2,wi2); FMA2(Nr,hj2,wj2); FMA2(Nr,hk2,wk2);    \
    FMA2(Pi,hr2,wi2); FMA2(Pi,hi2,wr2); FMA2(Pi,hk2,wj2); FMA2(Ni,hj2,wk2);    \
    FMA2(Pj,hr2,wj2); FMA2(Pj,hi2,wk2); FMA2(Pj,hj2,wr2); FMA2(Nj,hk2,wi2);    \
    FMA2(Pk,hr2,wk2); FMA2(Pk,hj2,wi2); FMA2(Pk,hk2,wr2); FMA2(Nk,hi2,wj2);    \
} while (0)

__device__ __forceinline__ float sig_f(float x) {
    return 1.0f / (1.0f + __expf(-x));
}
__device__ __forceinline__ float tanh_f(float x) {
    float e = __expf(2.0f * x);
    return 1.0f - 2.0f / (e + 1.0f);
}

// ---------------- weight packing ----------------
__global__ void qrn_prep(const float* __restrict__ wihr, const float* __restrict__ wihi,
                         const float* __restrict__ wihj, const float* __restrict__ wihk,
                         const float* __restrict__ whhr, const float* __restrict__ whhi,
                         const float* __restrict__ whhj, const float* __restrict__ whhk) {
    int idx = blockIdx.x * blockDim.x + threadIdx.x;
    if (idx >= 64 * 96) return;
    int u = idx / 96, jp = idx % 96;
    int c0 = u * GG + 2 * jp;
    ulonglong2 a, bv;
    a.x  = pk2(wihr[c0], wihr[c0 + 1]); a.y  = pk2(wihi[c0], wihi[c0 + 1]);
    bv.x = pk2(wihj[c0], wihj[c0 + 1]); bv.y = pk2(wihk[c0], wihk[c0 + 1]);
    g_wihA[idx] = a; g_wihB[idx] = bv;
    a.x  = pk2(whhr[c0], whhr[c0 + 1]); a.y  = pk2(whhi[c0], whhi[c0 + 1]);
    bv.x = pk2(whhj[c0], whhj[c0 + 1]); bv.y = pk2(whhk[c0], whhk[c0 + 1]);
    g_whhA[idx] = a; g_whhB[idx] = bv;
}

// ---------------- phase 1: gi = x @ W_ih + b_ih (full chip, serial) ----------------
#define GEMM_SMEM (98304 * 2 + 16384)
__global__ __launch_bounds__(384, 1) void qrn_gemm(const float* __restrict__ x,
                                                   const float* __restrict__ bih) {
    extern __shared__ char smem[];
    ulonglong2* swA = (ulonglong2*)smem;
    ulonglong2* swB = (ulonglong2*)(smem + 98304);
    float* xs = (float*)(smem + 196608);
    int t = threadIdx.x;
    for (int i = t; i < 6144; i += 384) { swA[i] = g_wihA[i]; swB[i] = g_wihB[i]; }
    int jp = t % 96, rg = t / 96;
    float2 bias2[4];
#pragma unroll
    for (int q = 0; q < 4; ++q) bias2[q] = *(const float2*)(bih + q * GG + 2 * jp);

    for (int tile = blockIdx.x; tile < NTILE; tile += gridDim.x) {
        __syncthreads();
        const float4* xt4 = (const float4*)(x + (size_t)tile * 4096);
        float4* xs4 = (float4*)xs;
        for (int i = t; i < 1024; i += 384) xs4[i] = xt4[i];
        __syncthreads();

        ull acc[4][8];
#pragma unroll
        for (int rr = 0; rr < 4; ++rr)
#pragma unroll
            for (int k = 0; k < 8; ++k) acc[rr][k] = 0ull;

#pragma unroll 4
        for (int u = 0; u < 64; ++u) {
            ulonglong2 wA = swA[u * 96 + jp];
            ulonglong2 wB = swB[u * 96 + jp];
#pragma unroll
            for (int rr = 0; rr < 4; ++rr) {
                const float* xr = xs + (rg * 4 + rr) * 256 + u;
                float hr = xr[0], hi = xr[64], hj = xr[128], hk = xr[192];
                ull hr2 = pk2(hr, hr), hi2 = pk2(hi, hi);
                ull hj2 = pk2(hj, hj), hk2 = pk2(hk, hk);
                QFMA16(hr2, hi2, hj2, hk2, wA.x, wA.y, wB.x, wB.y,
                       acc[rr][0], acc[rr][1], acc[rr][2], acc[rr][3],
                       acc[rr][4], acc[rr][5], acc[rr][6], acc[rr][7]);
            }
        }

#pragma unroll
        for (int rr = 0; rr < 4; ++rr) {
            float* go = g_gi + ((size_t)tile * 16 + rg * 4 + rr) * 768;
#pragma unroll
            for (int q = 0; q < 4; ++q) {
                float2 p = upk2(acc[rr][2 * q]);
                float2 n = upk2(acc[rr][2 * q + 1]);
                float2 o;
                o.x = p.x - n.x + bias2[q].x;
                o.y = p.y - n.y + bias2[q].y;
                *(float2*)(go + q * GG + 2 * jp) = o;
            }
        }
    }
}

// ---------------- phase 2: recurrence, 2-CTA cluster per batch ----------------
// Column split: rank r owns output units [32r, 32r+32) and computes the FULL
// K-sum (all 64 u) for its 96 base columns. Only new h (128 values per CTA)
// crosses DSMEM each step, written directly into both CTAs' h buffers.
#define REC_SMEM (114688 + 64)

__global__ __launch_bounds__(384, 1) __cluster_dims__(2, 1, 1)
void qrn_recur(const float* __restrict__ hx, const float* __restrict__ bhh,
               float* __restrict__ out, int out_size) {
    extern __shared__ char smem[];
    ulonglong2* swA = (ulonglong2*)smem;                 // 48KB: 64u x 48 local cp
    ulonglong2* swB = (ulonglong2*)(smem + 49152);       // 48KB
    float* red = (float*)(smem + 98304);                 // 12KB: 8 parts x 384
    float* h4  = (float*)(smem + 110592);                // 4KB: 2 bufs x 512 (dup pairs)
    ull*   mbar = (ull*)(smem + 114688);

    int t = threadIdx.x;
    unsigned rank;
    asm("mov.u32 %0, %%cluster_ctarank;" : "=r"(rank));
    int b = blockIdx.x >> 1;
    int cpl = t % 48, part = t / 48;                     // 48 col-pairs x 8 partitions

    // weights: local cpl=(g,vp) -> global col-pair jp = g*32 + 16*rank + vp
    for (int i = t; i < 3072; i += 384) {
        int lu = i / 48, c = i % 48, g = c / 16, vp = c % 16;
        int gidx = lu * 96 + g * 32 + 16 * (int)rank + vp;
        swA[i] = g_whhA[gidx];
        swB[i] = g_whhB[gidx];
    }
    // init h buffer 0 with hx (full vector, duplicated pairs)
    if (t < 256) {
        int qq = t >> 6, uu = t & 63;
        float hv = hx[b * 256 + t];
        h4[uu * 8 + 2 * qq]     = hv;
        h4[uu * 8 + 2 * qq + 1] = hv;
    }
    unsigned mbar_u = s2u(mbar);
    unsigned h4_u   = s2u(h4);
    if (t == 0)
        asm volatile("mbarrier.init.shared.b64 [%0], %1;" :: "r"(mbar_u), "r"(256u) : "memory");
    __syncthreads();
    asm volatile("barrier.cluster.arrive.aligned;" ::: "memory");
    asm volatile("barrier.cluster.wait.aligned;" ::: "memory");

    unsigned mbar_r0, mbar_r1, h4_r0, h4_r1;
    asm("mapa.shared::cluster.u32 %0, %1, %2;" : "=r"(mbar_r0) : "r"(mbar_u), "r"(0u));
    asm("mapa.shared::cluster.u32 %0, %1, %2;" : "=r"(mbar_r1) : "r"(mbar_u), "r"(1u));
    asm("mapa.shared::cluster.u32 %0, %1, %2;" : "=r"(h4_r0)   : "r"(h4_u),   "r"(0u));
    asm("mapa.shared::cluster.u32 %0, %1, %2;" : "=r"(h4_r1)   : "r"(h4_u),   "r"(1u));

    // owner state: thread t<128 owns (q = t>>5, vl = t&31), global unit gu
    int q = 0, vl = 0, gu = 0;
    float hcur = 0.f, bh0 = 0.f, bh1 = 0.f, bh2 = 0.f;
    float gc0 = 0.f, gc1 = 0.f, gc2 = 0.f;
    if (t < 128) {
        q = t >> 5; vl = t & 31; gu = 32 * (int)rank + vl;
        hcur = hx[b * 256 + q * 64 + gu];
        bh0 = bhh[q * GG + gu];
        bh1 = bhh[q * GG + 64 + gu];
        bh2 = bhh[q * GG + 128 + gu];
        const float* gp = g_gi + (size_t)b * 768 + q * GG + gu;
        gc0 = gp[0]; gc1 = gp[64]; gc2 = gp[128];
    }

#pragma unroll 1
    for (int step = 0; step < TT; ++step) {
        unsigned par = (unsigned)step & 1u;
        unsigned nb = par ^ 1u;

        // prefetch gi[step+1] (covered by the whole step)
        float gn0 = 0.f, gn1 = 0.f, gn2 = 0.f;
        if (t < 128 && step + 1 < TT) {
            const float* gp = g_gi + ((size_t)(step + 1) * BB + b) * 768 + q * GG + gu;
            gn0 = __ldcg(gp); gn1 = __ldcg(gp + 64); gn2 = __ldcg(gp + 128);
        }

        const float* hb = h4 + par * 512;
        ull Pr = 0, Nr = 0, Pi = 0, Ni = 0, Pj = 0, Nj = 0, Pk = 0, Nk = 0;
#pragma unroll
        for (int uu = 0; uu < 8; ++uu) {
            int u = part * 8 + uu;
            ulonglong2 wA = swA[u * 48 + cpl];
            ulonglong2 wB = swB[u * 48 + cpl];
            ulonglong2 hA = *(ulonglong2*)(hb + u * 8);       // {hr,hr,hi,hi}
            ulonglong2 hB = *(ulonglong2*)(hb + u * 8 + 4);   // {hj,hj,hk,hk}
            QFMA16(hA.x, hA.y, hB.x, hB.y, wA.x, wA.y, wB.x, wB.y,
                   Pr, Nr, Pi, Ni, Pj, Nj, Pk, Nk);
        }
        {
            float2 pr = upk2(Pr), nr = upk2(Nr), pi = upk2(Pi), ni = upk2(Ni);
            float2 pj = upk2(Pj), nj = upk2(Nj), pk = upk2(Pk), nk = upk2(Nk);
            float* rb = red + part * 384 + 2 * cpl;
            float2 v;
            v.x = pr.x - nr.x; v.y = pr.y - nr.y; *(float2*)(rb)       = v;
            v.x = pi.x - ni.x; v.y = pi.y - ni.y; *(float2*)(rb + 96)  = v;
            v.x = pj.x - nj.x; v.y = pj.y - nj.y; *(float2*)(rb + 192) = v;
            v.x = pk.x - nk.x; v.y = pk.y - nk.y; *(float2*)(rb + 288) = v;
        }
        __syncthreads();

        if (t < 128) {
            float gs0 = 0.f, gs1 = 0.f, gs2 = 0.f;
#pragma unroll
            for (int p = 0; p < 8; ++p) {
                const float* rp = red + p * 384 + q * 96 + vl;
                gs0 += rp[0]; gs1 += rp[32]; gs2 += rp[64];
            }
            float rg_ = sig_f(gc0 + gs0 + bh0);
            float zg  = sig_f(gc1 + gs1 + bh1);
            float ng  = tanh_f(gc2 + rg_ * (gs2 + bh2));
            hcur = ng + zg * (hcur - ng);
            out[((size_t)step * BB + b) * 256 + q * 64 + gu] = hcur;
            ull hp = pk2(hcur, hcur);
            unsigned off = (nb * 512u + (unsigned)gu * 8u + 2u * (unsigned)q) * 4u;
            asm volatile("st.shared::cluster.b64 [%0], %1;" :: "r"(h4_r0 + off), "l"(hp) : "memory");
            asm volatile("st.shared::cluster.b64 [%0], %1;" :: "r"(h4_r1 + off), "l"(hp) : "memory");
            asm volatile("mbarrier.arrive.release.cluster.shared::cluster.b64 _, [%0];"
                         :: "r"(mbar_r0) : "memory");
            asm volatile("mbarrier.arrive.release.cluster.shared::cluster.b64 _, [%0];"
                         :: "r"(mbar_r1) : "memory");
        }
        gc0 = gn0; gc1 = gn1; gc2 = gn2;

        // all threads wait for 256 arrivals (128 owners x 2 CTAs)
        unsigned done = 0;
        while (!done)
            asm volatile("{ .reg .pred p; "
                         "mbarrier.try_wait.parity.acquire.cluster.shared::cta.b64 p, [%1], %2, 0x989680; "
                         "selp.b32 %0, 1, 0, p; }"
                         : "=r"(done) : "r"(mbar_u), "r"(par) : "memory");
    }

    if (t < 128 && out_size >= OUT_MAIN + BB * 256)
        out[OUT_MAIN + b * 256 + q * 64 + gu] = hcur;

    asm volatile("barrier.cluster.arrive.aligned;" ::: "memory");
    asm volatile("barrier.cluster.wait.aligned;" ::: "memory");
}

extern "C" void kernel_launch(void* const* d_in, const int* in_sizes, int n_in,
                              void* d_out, int out_size) {
    const float* x    = (const float*)d_in[0];
    const float* hx   = (const float*)d_in[1];
    const float* wihr = (const float*)d_in[2];
    const float* wihi = (const float*)d_in[3];
    const float* wihj = (const float*)d_in[4];
    const float* wihk = (const float*)d_in[5];
    const float* whhr = (const float*)d_in[6];
    const float* whhi = (const float*)d_in[7];
    const float* whhj = (const float*)d_in[8];
    const float* whhk = (const float*)d_in[9];
    const float* bih  = (const float*)d_in[10];
    const float* bhh  = (const float*)d_in[11];
    float* out = (float*)d_out;

    qrn_prep<<<24, 256>>>(wihr, wihi, wihj, wihk, whhr, whhi, whhj, whhk);

    cudaFuncSetAttribute(qrn_gemm, cudaFuncAttributeMaxDynamicSharedMemorySize, GEMM_SMEM);
    qrn_gemm<<<148, 384, GEMM_SMEM>>>(x, bih);

    cudaFuncSetAttribute(qrn_recur, cudaFuncAttributeMaxDynamicSharedMemorySize, REC_SMEM);
    qrn_recur<<<128, 384, REC_SMEM>>>(hx, bhh, out, out_size);
}

// round 9
// speedup vs baseline: 1.1380x; 1.1380x over previous
#include <cuda_runtime.h>
#include <cuda_bf16.h>

#define TT 2048
#define BB 64
#define GG 192
#define OUT_MAIN 33554432
#define NTILE 8192

typedef unsigned long long ull;

// ---------------- device scratch (no cudaMalloc allowed) ----------------
__device__ float g_gi[(size_t)TT * BB * 768];          // input-side preactivations
__device__ ulonglong2 g_wihA[64 * 96];                 // {(r pair),(i pair)} per (u, col-pair)
__device__ ulonglong2 g_wihB[64 * 96];                 // {(j pair),(k pair)}
__device__ ulonglong2 g_whhA[64 * 96];
__device__ ulonglong2 g_whhB[64 * 96];

// ---------------- helpers ----------------
__device__ __forceinline__ ull pk2(float a, float b) {
    ull r; asm("mov.b64 %0, {%1,%2};" : "=l"(r) : "f"(a), "f"(b)); return r;
}
__device__ __forceinline__ float2 upk2(ull v) {
    float2 r; asm("mov.b64 {%0,%1}, %2;" : "=f"(r.x), "=f"(r.y) : "l"(v)); return r;
}
__device__ __forceinline__ unsigned s2u(const void* p) {
    unsigned a;
    asm("{ .reg .u64 t; cvta.to.shared.u64 t, %1; cvt.u32.u64 %0, t; }" : "=r"(a) : "l"(p));
    return a;
}
#define FMA2(acc, a, b) asm("fma.rn.f32x2 %0, %1, %2, %0;" : "+l"(acc) : "l"(a), "l"(b))

// Full quaternion (Hamilton) product contribution for one u and one column
// pair: 16 packed FMAs. P/N accumulator split avoids operand negation.
#define QFMA16(hr2,hi2,hj2,hk2, wr2,wi2,wj2,wk2, Pr,Nr,Pi,Ni,Pj,Nj,Pk,Nk) do { \
    FMA2(Pr,hr2,wr2); FMA2(Nr,hi2,wi2); FMA2(Nr,hj2,wj2); FMA2(Nr,hk2,wk2);    \
    FMA2(Pi,hr2,wi2); FMA2(Pi,hi2,wr2); FMA2(Pi,hk2,wj2); FMA2(Ni,hj2,wk2);    \
    FMA2(Pj,hr2,wj2); FMA2(Pj,hi2,wk2); FMA2(Pj,hj2,wr2); FMA2(Nj,hk2,wi2);    \
    FMA2(Pk,hr2,wk2); FMA2(Pk,hj2,wi2); FMA2(Pk,hk2,wr2); FMA2(Nk,hi2,wj2);    \
} while (0)

__device__ __forceinline__ float sig_f(float x) {
    return 1.0f / (1.0f + __expf(-x));
}
__device__ __forceinline__ float tanh_f(float x) {
    float e = __expf(2.0f * x);
    return 1.0f - 2.0f / (e + 1.0f);
}

// ---------------- weight packing ----------------
__global__ void qrn_prep(const float* __restrict__ wihr, const float* __restrict__ wihi,
                         const float* __restrict__ wihj, const float* __restrict__ wihk,
                         const float* __restrict__ whhr, const float* __restrict__ whhi,
                         const float* __restrict__ whhj, const float* __restrict__ whhk) {
    int idx = blockIdx.x * blockDim.x + threadIdx.x;
    if (idx >= 64 * 96) return;
    int u = idx / 96, jp = idx % 96;
    int c0 = u * GG + 2 * jp;
    ulonglong2 a, bv;
    a.x  = pk2(wihr[c0], wihr[c0 + 1]); a.y  = pk2(wihi[c0], wihi[c0 + 1]);
    bv.x = pk2(wihj[c0], wihj[c0 + 1]); bv.y = pk2(wihk[c0], wihk[c0 + 1]);
    g_wihA[idx] = a; g_wihB[idx] = bv;
    a.x  = pk2(whhr[c0], whhr[c0 + 1]); a.y  = pk2(whhi[c0], whhi[c0 + 1]);
    bv.x = pk2(whhj[c0], whhj[c0 + 1]); bv.y = pk2(whhk[c0], whhk[c0 + 1]);
    g_whhA[idx] = a; g_whhB[idx] = bv;
}

// ---------------- phase 1: gi = x @ W_ih + b_ih (full chip, serial) ----------------
#define GEMM_SMEM (98304 * 2 + 16384)
__global__ __launch_bounds__(384, 1) void qrn_gemm(const float* __restrict__ x,
                                                   const float* __restrict__ bih) {
    extern __shared__ char smem[];
    ulonglong2* swA = (ulonglong2*)smem;
    ulonglong2* swB = (ulonglong2*)(smem + 98304);
    float* xs = (float*)(smem + 196608);
    int t = threadIdx.x;
    for (int i = t; i < 6144; i += 384) { swA[i] = g_wihA[i]; swB[i] = g_wihB[i]; }
    int jp = t % 96, rg = t / 96;
    float2 bias2[4];
#pragma unroll
    for (int q = 0; q < 4; ++q) bias2[q] = *(const float2*)(bih + q * GG + 2 * jp);

    for (int tile = blockIdx.x; tile < NTILE; tile += gridDim.x) {
        __syncthreads();
        const float4* xt4 = (const float4*)(x + (size_t)tile * 4096);
        float4* xs4 = (float4*)xs;
        for (int i = t; i < 1024; i += 384) xs4[i] = xt4[i];
        __syncthreads();

        ull acc[4][8];
#pragma unroll
        for (int rr = 0; rr < 4; ++rr)
#pragma unroll
            for (int k = 0; k < 8; ++k) acc[rr][k] = 0ull;

#pragma unroll 4
        for (int u = 0; u < 64; ++u) {
            ulonglong2 wA = swA[u * 96 + jp];
            ulonglong2 wB = swB[u * 96 + jp];
#pragma unroll
            for (int rr = 0; rr < 4; ++rr) {
                const float* xr = xs + (rg * 4 + rr) * 256 + u;
                float hr = xr[0], hi = xr[64], hj = xr[128], hk = xr[192];
                ull hr2 = pk2(hr, hr), hi2 = pk2(hi, hi);
                ull hj2 = pk2(hj, hj), hk2 = pk2(hk, hk);
                QFMA16(hr2, hi2, hj2, hk2, wA.x, wA.y, wB.x, wB.y,
                       acc[rr][0], acc[rr][1], acc[rr][2], acc[rr][3],
                       acc[rr][4], acc[rr][5], acc[rr][6], acc[rr][7]);
            }
        }

#pragma unroll
        for (int rr = 0; rr < 4; ++rr) {
            float* go = g_gi + ((size_t)tile * 16 + rg * 4 + rr) * 768;
#pragma unroll
            for (int q = 0; q < 4; ++q) {
                float2 p = upk2(acc[rr][2 * q]);
                float2 n = upk2(acc[rr][2 * q + 1]);
                float2 o;
                o.x = p.x - n.x + bias2[q].x;
                o.y = p.y - n.y + bias2[q].y;
                *(float2*)(go + q * GG + 2 * jp) = o;
            }
        }
    }
}

// ---------------- phase 2: recurrence, 2-CTA cluster per batch (K-split) ----------------
// Rank r sums u in [32r, 32r+32) for ALL 768 columns; W_hh slice lives in
// REGISTERS (64 f32/thread). 768 partial sums exchanged via DSMEM per step;
// both CTAs redundantly compute gates. acquire.cta wait (release from peer).
__global__ __launch_bounds__(384, 1) __cluster_dims__(2, 1, 1)
void qrn_recur(const float* __restrict__ hx, const float* __restrict__ bhh,
               float* __restrict__ out, int out_size) {
    __shared__ __align__(16) float red[4 * 768];     // 12KB: 4 partition partials
    __shared__ __align__(16) float h4dup[512];       // 2KB: {hr,hr,hi,hi,hj,hj,hk,hk}/u
    __shared__ __align__(16) float pbuf[2 * 768];    // 6KB: peer partials, x2 parity
    __shared__ __align__(8)  ull mbar[1];

    int t = threadIdx.x;
    unsigned rank;
    asm("mov.u32 %0, %%cluster_ctarank;" : "=r"(rank));
    int b = blockIdx.x >> 1;
    int jp = t % 96, up = t / 96, ub = up * 8;
    int ru = (int)rank * 32;

    // register-resident W_hh slice: u = ru + ub + uu
    ulonglong2 wAr[8], wBr[8];
#pragma unroll
    for (int uu = 0; uu < 8; ++uu) {
        wAr[uu] = g_whhA[(ru + ub + uu) * 96 + jp];
        wBr[uu] = g_whhB[(ru + ub + uu) * 96 + jp];
    }

    unsigned mbar_u = s2u(mbar);
    unsigned pbuf_u = s2u(pbuf);
    unsigned peer = rank ^ 1u;
    unsigned peer_mbar, peer_pbuf;
    asm("mapa.shared::cluster.u32 %0, %1, %2;" : "=r"(peer_mbar) : "r"(mbar_u), "r"(peer));
    asm("mapa.shared::cluster.u32 %0, %1, %2;" : "=r"(peer_pbuf) : "r"(pbuf_u), "r"(peer));

    float hcur = 0.f, bh0 = 0.f, bh1 = 0.f, bh2 = 0.f;
    int q = 0, u = 0, o0 = 0;
    if (t < 256) {
        q = t >> 6; u = t & 63; o0 = q * GG + u;
        hcur = hx[b * 256 + t];
        h4dup[u * 8 + 2 * q]     = hcur;
        h4dup[u * 8 + 2 * q + 1] = hcur;
        bh0 = bhh[o0]; bh1 = bhh[o0 + 64]; bh2 = bhh[o0 + 128];
    }
    if (t == 0)
        asm volatile("mbarrier.init.shared.b64 [%0], %1;" :: "r"(mbar_u), "r"(256u) : "memory");
    __syncthreads();
    asm volatile("barrier.cluster.arrive.aligned;" ::: "memory");
    asm volatile("barrier.cluster.wait.aligned;" ::: "memory");

    // preload gi[0]
    float gc0 = 0.f, gc1 = 0.f, gc2 = 0.f;
    if (t < 256) {
        const float* gp = g_gi + (size_t)b * 768 + o0;
        gc0 = gp[0]; gc1 = gp[64]; gc2 = gp[128];
    }

#pragma unroll 1
    for (int step = 0; step < TT; ++step) {
        unsigned par = (unsigned)step & 1u;
        // prefetch gi[step+1] (covered by the whole step)
        float gn0 = 0.f, gn1 = 0.f, gn2 = 0.f;
        if (t < 256 && step + 1 < TT) {
            const float* gp = g_gi + ((size_t)(step + 1) * BB + b) * 768 + o0;
            gn0 = __ldcg(gp); gn1 = __ldcg(gp + 64); gn2 = __ldcg(gp + 128);
        }

        ull Pr = 0, Nr = 0, Pi = 0, Ni = 0, Pj = 0, Nj = 0, Pk = 0, Nk = 0;
#pragma unroll
        for (int uu = 0; uu < 8; ++uu) {
            int gu = ru + ub + uu;
            ulonglong2 hA = *(ulonglong2*)(h4dup + gu * 8);       // {hr,hr,hi,hi}
            ulonglong2 hB = *(ulonglong2*)(h4dup + gu * 8 + 4);   // {hj,hj,hk,hk}
            QFMA16(hA.x, hA.y, hB.x, hB.y, wAr[uu].x, wAr[uu].y, wBr[uu].x, wBr[uu].y,
                   Pr, Nr, Pi, Ni, Pj, Nj, Pk, Nk);
        }
        {
            float2 pr = upk2(Pr), nr = upk2(Nr), pi = upk2(Pi), ni = upk2(Ni);
            float2 pj = upk2(Pj), nj = upk2(Nj), pk = upk2(Pk), nk = upk2(Nk);
            float* rb = red + up * 768 + 2 * jp;
            float2 v;
            v.x = pr.x - nr.x; v.y = pr.y - nr.y; *(float2*)(rb)       = v;
            v.x = pi.x - ni.x; v.y = pi.y - ni.y; *(float2*)(rb + 192) = v;
            v.x = pj.x - nj.x; v.y = pj.y - nj.y; *(float2*)(rb + 384) = v;
            v.x = pk.x - nk.x; v.y = pk.y - nk.y; *(float2*)(rb + 576) = v;
        }
        __syncthreads();

        if (t < 256) {
            // local half-sum for this output
            float p0 = red[o0]       + red[768 + o0]       + red[1536 + o0]       + red[2304 + o0];
            float p1 = red[o0 + 64]  + red[768 + o0 + 64]  + red[1536 + o0 + 64]  + red[2304 + o0 + 64];
            float p2 = red[o0 + 128] + red[768 + o0 + 128] + red[1536 + o0 + 128] + red[2304 + o0 + 128];
            // ship to peer (parity-buffered), then signal peer's mbar (release)
            unsigned dst = peer_pbuf + ((par * 768u + (unsigned)o0) << 2);
            asm volatile("st.shared::cluster.b32 [%0], %1;" :: "r"(dst),        "r"(__float_as_uint(p0)) : "memory");
            asm volatile("st.shared::cluster.b32 [%0], %1;" :: "r"(dst + 256u), "r"(__float_as_uint(p1)) : "memory");
            asm volatile("st.shared::cluster.b32 [%0], %1;" :: "r"(dst + 512u), "r"(__float_as_uint(p2)) : "memory");
            asm volatile("mbarrier.arrive.release.cluster.shared::cluster.b64 _, [%0];"
                         :: "r"(peer_mbar) : "memory");
            // wait for peer's 256 arrivals on local mbar (acquire.cta: flag+data local)
            unsigned done = 0;
            while (!done)
                asm volatile("{ .reg .pred p; "
                             "mbarrier.try_wait.parity.acquire.cta.shared::cta.b64 p, [%1], %2, 0x989680; "
                             "selp.b32 %0, 1, 0, p; }"
                             : "=r"(done) : "r"(mbar_u), "r"(par) : "memory");
            const float* pb = pbuf + par * 768;
            float gh0 = p0 + pb[o0];
            float gh1 = p1 + pb[o0 + 64];
            float gh2 = p2 + pb[o0 + 128];
            float rg_ = sig_f(gc0 + gh0 + bh0);
            float zg  = sig_f(gc1 + gh1 + bh1);
            float ng  = tanh_f(gc2 + rg_ * (gh2 + bh2));
            hcur = ng + zg * (hcur - ng);
            float2 hd; hd.x = hcur; hd.y = hcur;
            *(float2*)(h4dup + u * 8 + 2 * q) = hd;
            if (rank == 0)
                out[((size_t)step * BB + b) * 256 + t] = hcur;
        }
        gc0 = gn0; gc1 = gn1; gc2 = gn2;
        __syncthreads();
    }

    if (rank == 0 && t < 256 && out_size >= OUT_MAIN + BB * 256)
        out[OUT_MAIN + b * 256 + t] = hcur;

    asm volatile("barrier.cluster.arrive.aligned;" ::: "memory");
    asm volatile("barrier.cluster.wait.aligned;" ::: "memory");
}

extern "C" void kernel_launch(void* const* d_in, const int* in_sizes, int n_in,
                              void* d_out, int out_size) {
    const float* x    = (const float*)d_in[0];
    const float* hx   = (const float*)d_in[1];
    const float* wihr = (const float*)d_in[2];
    const float* wihi = (const float*)d_in[3];
    const float* wihj = (const float*)d_in[4];
    const float* wihk = (const float*)d_in[5];
    const float* whhr = (const float*)d_in[6];
    const float* whhi = (const float*)d_in[7];
    const float* whhj = (const float*)d_in[8];
    const float* whhk = (const float*)d_in[9];
    const float* bih  = (const float*)d_in[10];
    const float* bhh  = (const float*)d_in[11];
    float* out = (float*)d_out;

    qrn_prep<<<24, 256>>>(wihr, wihi, wihj, wihk, whhr, whhi, whhj, whhk);

    cudaFuncSetAttribute(qrn_gemm, cudaFuncAttributeMaxDynamicSharedMemorySize, GEMM_SMEM);
    qrn_gemm<<<148, 384, GEMM_SMEM>>>(x, bih);

    qrn_recur<<<128, 384>>>(hx, bhh, out, out_size);
}